// round 16
// baseline (speedup 1.0000x reference)
#include <cuda_runtime.h>
#include <cuda_bf16.h>
#include <cstdint>

#define NB 64
#define UD 512
#define VD 32000
#define TS 20
#define ZN 2048
#define GK 1024
#define GKS 8
#define NTILES 250
#define NCHUNK 16
#define GRID_F (NTILES + 64)   // 250 logits + 64 h-gate blocks

// ---------------- persistent device scratch ----------------
__device__ float g_h[NB * UD];
__device__ float g_c[NB * UD];
__device__ float g_zpart[GKS][NB * ZN];
__device__ unsigned long long g_amax[NB];
__device__ unsigned int g_barrier;   // step_front barrier (128 arrivals)
__device__ unsigned int g_bar1;      // fused barrier1 (314 arrivals/step)
__device__ unsigned int g_bar2;      // fused barrier2 (64 arrivals/step)
__device__ __align__(16) unsigned char g_WdT[(size_t)NTILES * NCHUNK * 2 * 8192];
__device__ __nv_bfloat16 g_Wg0[(size_t)GK * ZN];
__device__ __nv_bfloat16 g_Wg1[(size_t)GK * ZN];
__device__ __nv_bfloat16 g_Al0[NB * UD];
__device__ __nv_bfloat16 g_Al1[NB * UD];

// ---------------- helpers ----------------
__device__ __forceinline__ unsigned long long enc_max(float v, int col) {
    unsigned int u = __float_as_uint(v);
    unsigned int key = (u & 0x80000000u) ? ~u : (u | 0x80000000u);
    return ((unsigned long long)key << 32) |
           (unsigned long long)(0xFFFFFFFFu - (unsigned int)col);
}
__device__ __forceinline__ int dec_idx(unsigned long long e) {
    return (int)(0xFFFFFFFFu - (unsigned int)(e & 0xFFFFFFFFull));
}
__device__ __forceinline__ void split2(float v, __nv_bfloat16& b0, __nv_bfloat16& b1) {
    b0 = __float2bfloat16(v);
    b1 = __float2bfloat16(v - __bfloat162float(b0));
}
__device__ __forceinline__ uint32_t smem_u32(const void* p) {
    uint32_t a;
    asm("{ .reg .u64 t; cvta.to.shared.u64 t, %1; cvt.u32.u64 %0, t; }"
        : "=r"(a) : "l"(p));
    return a;
}
__device__ __forceinline__ void cp16(uint32_t dst, const void* src) {
    asm volatile("cp.async.cg.shared.global [%0], [%1], 16;" :: "r"(dst), "l"(src));
}
#define CP_COMMIT() asm volatile("cp.async.commit_group;" ::: "memory")
#define CP_WAIT(n)  asm volatile("cp.async.wait_group %0;" :: "n"(n) : "memory")

__device__ __forceinline__ void ldm_x4(uint32_t* r, uint32_t addr) {
    asm volatile("ldmatrix.sync.aligned.m8n8.x4.shared.b16 {%0,%1,%2,%3}, [%4];"
        : "=r"(r[0]), "=r"(r[1]), "=r"(r[2]), "=r"(r[3]) : "r"(addr));
}
__device__ __forceinline__ void ldm_x4t(uint32_t* r, uint32_t addr) {
    asm volatile("ldmatrix.sync.aligned.m8n8.x4.trans.shared.b16 {%0,%1,%2,%3}, [%4];"
        : "=r"(r[0]), "=r"(r[1]), "=r"(r[2]), "=r"(r[3]) : "r"(addr));
}
__device__ __forceinline__ void mma16816(float* c, const uint32_t* a, const uint32_t* b) {
    asm volatile(
        "mma.sync.aligned.m16n8k16.row.col.f32.bf16.bf16.f32 "
        "{%0,%1,%2,%3}, {%4,%5,%6,%7}, {%8,%9}, {%0,%1,%2,%3};"
        : "+f"(c[0]), "+f"(c[1]), "+f"(c[2]), "+f"(c[3])
        : "r"(a[0]), "r"(a[1]), "r"(a[2]), "r"(a[3]), "r"(b[0]), "r"(b[1]));
}

// ============================================================================
// one-time preps
// ============================================================================
__global__ void __launch_bounds__(256) prep_WdT_kernel(const float* __restrict__ Wd) {
    int id = blockIdx.x * blockDim.x + threadIdx.x;
    if (id >= NTILES * NCHUNK * 32 * 16) return;
    int c16 = id & 15;
    int r   = (id >> 4) & 31;
    int ch  = (id >> 9) & 15;
    int nt  = id >> 13;
    int k = ch * 32 + r;
    int n = nt * 128 + c16 * 8;
    const float* src = Wd + (size_t)k * VD + n;
    float4 v0 = *(const float4*)src;
    float4 v1 = *(const float4*)(src + 4);
    __nv_bfloat16 lo[8], hi[8];
    split2(v0.x, lo[0], hi[0]); split2(v0.y, lo[1], hi[1]);
    split2(v0.z, lo[2], hi[2]); split2(v0.w, lo[3], hi[3]);
    split2(v1.x, lo[4], hi[4]); split2(v1.y, lo[5], hi[5]);
    split2(v1.z, lo[6], hi[6]); split2(v1.w, lo[7], hi[7]);
    uint32_t off = (uint32_t)r * 256 + (uint32_t)(c16 ^ ((r & 7) << 1)) * 16;
    unsigned char* base = g_WdT + ((size_t)(nt * NCHUNK + ch) * 2) * 8192;
    *(uint4*)(base + off)        = *(uint4*)lo;
    *(uint4*)(base + 8192 + off) = *(uint4*)hi;
}

__global__ void __launch_bounds__(256) prep_Wg_kernel(
    const float* __restrict__ Wx, const float* __restrict__ Wh) {
    int id = blockIdx.x * blockDim.x + threadIdx.x;
    if (id >= GK * ZN) return;
    int k = id >> 11, n = id & (ZN - 1);
    float v = (k < UD) ? Wx[(size_t)k * ZN + n] : Wh[(size_t)(k - UD) * ZN + n];
    __nv_bfloat16 b0, b1;
    split2(v, b0, b1);
    g_Wg0[id] = b0; g_Wg1[id] = b1;
}

// ============================================================================
// STEP FRONT (t=0 only): proven 256-thread fused gate+barrier+update.
// ============================================================================
#define FA_ST 272
#define FB_ST 272
#define FSA(spl)      ((spl) * 17408u)
#define FSB(buf, spl) (34816u + ((buf) * 2 + (spl)) * 17408u)
#define FSMEM (34816 + 69632)

__global__ void __launch_bounds__(256, 1) step_front_kernel(
    const float* __restrict__ h0, const float* __restrict__ c0,
    const float* __restrict__ emb, const float* __restrict__ b_lstm)
{
    extern __shared__ unsigned char smem[];
    const uint32_t smb = smem_u32(smem);
    const int tid = threadIdx.x, wid = tid >> 5, lane = tid & 31;
    const int wm = wid & 1, wn = wid >> 1;
    const int n0 = blockIdx.x * 128;
    const int ks = blockIdx.y;
    const int kbase = ks * 128;

    const __nv_bfloat16* Bsrc[2] = { g_Wg0, g_Wg1 };

#pragma unroll
    for (int ch = 0; ch < 2; ch++) {
        int kc = kbase + ch * 64;
#pragma unroll
        for (int j = 0; j < 8; j++) {
            int i = tid + j * 256;
            int s = i >> 10, rem = i & 1023, r = rem >> 4, c16 = rem & 15;
            cp16(smb + FSB(ch, s) + r * FB_ST + c16 * 16,
                 Bsrc[s] + (size_t)(kc + r) * ZN + n0 + c16 * 8);
        }
        CP_COMMIT();
    }

    {
        const int row = tid >> 2;
        const int cbase = (tid & 3) * 32;
        const float* src = (ks < 4)
            ? emb + (size_t)1 * UD + kbase + cbase
            : h0 + row * UD + (ks - 4) * 128 + cbase;
        __nv_bfloat16* a0 = (__nv_bfloat16*)(smem + FSA(0) + row * FA_ST) + cbase;
        __nv_bfloat16* a1 = (__nv_bfloat16*)(smem + FSA(1) + row * FA_ST) + cbase;
#pragma unroll
        for (int q = 0; q < 8; q++) {
            float4 v = *(const float4*)(src + q * 4);
            __nv_bfloat16 lo, hi;
            split2(v.x, lo, hi); a0[q * 4 + 0] = lo; a1[q * 4 + 0] = hi;
            split2(v.y, lo, hi); a0[q * 4 + 1] = lo; a1[q * 4 + 1] = hi;
            split2(v.z, lo, hi); a0[q * 4 + 2] = lo; a1[q * 4 + 2] = hi;
            split2(v.w, lo, hi); a0[q * 4 + 3] = lo; a1[q * 4 + 3] = hi;
        }
    }

    float acc[2][4][4];
#pragma unroll
    for (int i = 0; i < 2; i++)
#pragma unroll
        for (int j = 0; j < 4; j++)
#pragma unroll
            for (int q = 0; q < 4; q++) acc[i][j][q] = 0.f;

#pragma unroll
    for (int ch = 0; ch < 2; ch++) {
        if (ch == 0) { CP_WAIT(1); } else { CP_WAIT(0); }
        __syncthreads();
#pragma unroll
        for (int kf = 0; kf < 4; kf++) {
            uint32_t a0[2][4], a1[2][4];
#pragma unroll
            for (int mf = 0; mf < 2; mf++) {
                uint32_t arow = (wm * 32 + mf * 16 + (lane & 15)) * FA_ST
                              + ch * 128 + kf * 32 + (lane >> 4) * 16;
                ldm_x4(a0[mf], smb + FSA(0) + arow);
                ldm_x4(a1[mf], smb + FSA(1) + arow);
            }
#pragma unroll
            for (int nt = 0; nt < 2; nt++) {
                uint32_t b0[4], b1[4];
                uint32_t boff = (kf * 16 + (lane & 15)) * FB_ST
                              + (wn * 32 + nt * 16) * 2 + (lane >> 4) * 16;
                ldm_x4t(b0, smb + FSB(ch, 0) + boff);
                ldm_x4t(b1, smb + FSB(ch, 1) + boff);
#pragma unroll
                for (int mf = 0; mf < 2; mf++) {
                    mma16816(acc[mf][nt * 2],     a0[mf], b0);
                    mma16816(acc[mf][nt * 2],     a1[mf], b0);
                    mma16816(acc[mf][nt * 2],     a0[mf], b1);
                    mma16816(acc[mf][nt * 2 + 1], a0[mf], b0 + 2);
                    mma16816(acc[mf][nt * 2 + 1], a1[mf], b0 + 2);
                    mma16816(acc[mf][nt * 2 + 1], a0[mf], b1 + 2);
                }
            }
        }
        if (ch == 0) __syncthreads();
    }

    float* zp = g_zpart[ks];
#pragma unroll
    for (int mf = 0; mf < 2; mf++) {
#pragma unroll
        for (int nti = 0; nti < 4; nti++) {
            int r0 = wm * 32 + mf * 16 + (lane >> 2);
            int col = n0 + wn * 32 + nti * 8 + (lane & 3) * 2;
            *(float2*)&zp[(size_t)r0 * ZN + col] =
                make_float2(acc[mf][nti][0], acc[mf][nti][1]);
            *(float2*)&zp[(size_t)(r0 + 8) * ZN + col] =
                make_float2(acc[mf][nti][2], acc[mf][nti][3]);
        }
    }

    __threadfence();
    __syncthreads();
    if (tid == 0) {
        unsigned int ticket = atomicAdd(&g_barrier, 1u);
        unsigned int target = (ticket / 128u + 1u) * 128u;
        while (*(volatile unsigned int*)&g_barrier < target) __nanosleep(32);
        __threadfence();
    }
    __syncthreads();

    {
        int blkLin = blockIdx.y * 16 + blockIdx.x;
        int id = blkLin * 256 + tid;
        int b = id >> 9, u = id & 511;
        size_t base = (size_t)b * ZN;
        float zi = 0.f, zf = 0.f, zg = 0.f, zo = 0.f;
#pragma unroll
        for (int s = 0; s < GKS; s++) {
            zi += __ldcg(&g_zpart[s][base + u]);
            zf += __ldcg(&g_zpart[s][base + 512 + u]);
            zg += __ldcg(&g_zpart[s][base + 1024 + u]);
            zo += __ldcg(&g_zpart[s][base + 1536 + u]);
        }
        zi += b_lstm[u];        zf += b_lstm[512 + u];
        zg += b_lstm[1024 + u]; zo += b_lstm[1536 + u];

        float cp = c0[id];
        float si = 1.f / (1.f + expf(-zi));
        float sf = 1.f / (1.f + expf(-zf));
        float so = 1.f / (1.f + expf(-zo));
        float tg = tanhf(zg);
        float cn = sf * cp + si * tg;
        float hn = so * tanhf(cn);
        g_c[id] = cn;
        g_h[id] = hn;

        __nv_bfloat16 lo, hi;
        split2(hn, lo, hi);
        g_Al0[id] = lo; g_Al1[id] = hi;
        if (u == 0) g_amax[b] = 0ull;
    }
}

// ============================================================================
// GATE TILE (device fn): one 64x128 gate tile over K=128 (2 chunks of 64),
//   single B buffer (reloaded). Smem: GA 0..34816, GB 34816..69632.
// ============================================================================
#define GA(spl)      ((spl) * 17408u)
#define GB(spl)      (34816u + (spl) * 17408u)

__device__ __forceinline__ void gate_tile(
    unsigned char* smem, uint32_t smb, int tid,
    const float* a_src, int kbase, int zidx, int n0g)
{
    const int wid = tid >> 5, lane = tid & 31;
    const int wm = wid & 1, wn = wid >> 1;
    const __nv_bfloat16* Bsrc[2] = { g_Wg0, g_Wg1 };

    auto load_gate_chunk = [&](int ch) {
        int kc = kbase + ch * 64;
#pragma unroll
        for (int j = 0; j < 8; j++) {
            int i = tid + j * 256;
            int s = i >> 10, rem = i & 1023, r = rem >> 4, c16 = rem & 15;
            cp16(smb + GB(s) + r * FB_ST + c16 * 16,
                 Bsrc[s] + (size_t)(kc + r) * ZN + n0g + c16 * 8);
        }
        CP_COMMIT();
    };
    load_gate_chunk(0);

    {
        const int row = tid >> 2;
        __nv_bfloat16* a0 = (__nv_bfloat16*)(smem + GA(0) + row * FA_ST) + (tid & 3) * 32;
        __nv_bfloat16* a1 = (__nv_bfloat16*)(smem + GA(1) + row * FA_ST) + (tid & 3) * 32;
#pragma unroll
        for (int q = 0; q < 8; q++) {
            float4 v = *(const float4*)(a_src + q * 4);
            __nv_bfloat16 lo, hi;
            split2(v.x, lo, hi); a0[q * 4 + 0] = lo; a1[q * 4 + 0] = hi;
            split2(v.y, lo, hi); a0[q * 4 + 1] = lo; a1[q * 4 + 1] = hi;
            split2(v.z, lo, hi); a0[q * 4 + 2] = lo; a1[q * 4 + 2] = hi;
            split2(v.w, lo, hi); a0[q * 4 + 3] = lo; a1[q * 4 + 3] = hi;
        }
    }

    float acc[2][4][4];
#pragma unroll
    for (int i = 0; i < 2; i++)
#pragma unroll
        for (int j = 0; j < 4; j++)
#pragma unroll
            for (int q = 0; q < 4; q++) acc[i][j][q] = 0.f;

#pragma unroll
    for (int ch = 0; ch < 2; ch++) {
        CP_WAIT(0);
        __syncthreads();
#pragma unroll
        for (int kf = 0; kf < 4; kf++) {
            uint32_t a0[2][4], a1[2][4];
#pragma unroll
            for (int mf = 0; mf < 2; mf++) {
                uint32_t arow = (wm * 32 + mf * 16 + (lane & 15)) * FA_ST
                              + ch * 128 + kf * 32 + (lane >> 4) * 16;
                ldm_x4(a0[mf], smb + GA(0) + arow);
                ldm_x4(a1[mf], smb + GA(1) + arow);
            }
#pragma unroll
            for (int nt = 0; nt < 2; nt++) {
                uint32_t b0[4], b1[4];
                uint32_t boff = (kf * 16 + (lane & 15)) * FB_ST
                              + (wn * 32 + nt * 16) * 2 + (lane >> 4) * 16;
                ldm_x4t(b0, smb + GB(0) + boff);
                ldm_x4t(b1, smb + GB(1) + boff);
#pragma unroll
                for (int mf = 0; mf < 2; mf++) {
                    mma16816(acc[mf][nt * 2],     a0[mf], b0);
                    mma16816(acc[mf][nt * 2],     a1[mf], b0);
                    mma16816(acc[mf][nt * 2],     a0[mf], b1);
                    mma16816(acc[mf][nt * 2 + 1], a0[mf], b0 + 2);
                    mma16816(acc[mf][nt * 2 + 1], a1[mf], b0 + 2);
                    mma16816(acc[mf][nt * 2 + 1], a0[mf], b1 + 2);
                }
            }
        }
        if (ch == 0) {
            __syncthreads();
            load_gate_chunk(1);
        }
    }

    float* zp = g_zpart[zidx];
#pragma unroll
    for (int mf = 0; mf < 2; mf++) {
#pragma unroll
        for (int nti = 0; nti < 4; nti++) {
            int r0 = wm * 32 + mf * 16 + (lane >> 2);
            int col = n0g + wn * 32 + nti * 8 + (lane & 3) * 2;
            *(float2*)&zp[(size_t)r0 * ZN + col] =
                make_float2(acc[mf][nti][0], acc[mf][nti][1]);
            *(float2*)&zp[(size_t)(r0 + 8) * ZN + col] =
                make_float2(acc[mf][nti][2], acc[mf][nti][3]);
        }
    }
}

// ============================================================================
// FUSED (grid 314, 3 blocks/SM):
//   blocks 250-313: h-half gate for t+1 (runs CONCURRENT with logits) -> bar1
//   blocks 0-249:   logits(t) -> bar1; blocks 0-63 continue:
//                   emb-half gate(t+1) -> bar2(64) -> LSTM update (2 elem/thr)
// ============================================================================
#define LSA(st, spl) ((st) * 24576u + (spl) * 4096u)
#define LSB(st, spl) ((st) * 24576u + 8192u + (spl) * 8192u)
#define LSAMAX 73728
#define LSMEM  74240

__global__ void __launch_bounds__(256, 3) fused_step_kernel(
    const float* __restrict__ bd, float* __restrict__ out,
    const float* __restrict__ emb, const float* __restrict__ b_lstm, int t)
{
    extern __shared__ unsigned char smem[];
    const uint32_t smb = smem_u32(smem);
    const int tid = threadIdx.x, wid = tid >> 5, lane = tid & 31;
    const int wm = wid & 1, wn = wid >> 1;       // 2m x 4n

    if (blockIdx.x >= NTILES) {
        // ---- h-half gate for step t+1: depends only on g_h (ready now) ----
        if (t < TS - 1) {
            int idx = (int)blockIdx.x - NTILES;   // 0..63
            int bx = idx & 15, ks = 4 + (idx >> 4);
            const float* a_src = g_h + (tid >> 2) * UD + (ks - 4) * 128 + (tid & 3) * 32;
            gate_tile(smem, smb, tid, a_src, ks * 128, ks, bx * 128);
            __threadfence();
            __syncthreads();
            if (tid == 0) atomicAdd(&g_bar1, 1u);
        }
        return;
    }

    unsigned long long* samax = (unsigned long long*)(smem + LSAMAX);
    const int nt_idx = (t & 1) ? (249 - (int)blockIdx.x) : (int)blockIdx.x;
    const int v0 = nt_idx * 128;

    if (tid < NB) samax[tid] = 0ull;

    {   // ================= PHASE 1: logits GEMM (R15, unchanged) =================
        const __nv_bfloat16* Asrc[2] = { g_Al0, g_Al1 };
        const unsigned char* wt_base = g_WdT + ((size_t)nt_idx * NCHUNK * 2) * 8192;

        float acc[2][4][4];
#pragma unroll
        for (int i = 0; i < 2; i++)
#pragma unroll
            for (int j = 0; j < 4; j++)
#pragma unroll
                for (int q = 0; q < 4; q++) acc[i][j][q] = 0.f;

        auto load_chunk = [&](int ch, int st) {
            int kc = ch * 32;
#pragma unroll
            for (int j = 0; j < 2; j++) {
                int i = tid + j * 256;
                int s = i >> 8, rem = i & 255, r = rem >> 2, c4 = rem & 3;
                cp16(smb + LSA(st, s) + r * 64 + ((c4 ^ ((r >> 1) & 3)) << 4),
                     Asrc[s] + (size_t)r * UD + kc + c4 * 8);
            }
            const unsigned char* src = wt_base + ((size_t)ch * 2) * 8192;
#pragma unroll
            for (int j = 0; j < 4; j++) {
                int i = tid + j * 256;
                cp16(smb + LSB(st, 0) + (uint32_t)i * 16, src + (size_t)i * 16);
            }
            CP_COMMIT();
        };

        load_chunk(0, 0);
        load_chunk(1, 1);

#pragma unroll
        for (int ch = 0; ch < 16; ch++) {
            if (ch < 15) { CP_WAIT(1); } else { CP_WAIT(0); }
            __syncthreads();
            if (ch + 2 < 16) load_chunk(ch + 2, (ch + 2) % 3);
            const int st = ch % 3;
#pragma unroll
            for (int kf = 0; kf < 2; kf++) {
                uint32_t a0[2][4], a1[2][4];
#pragma unroll
                for (int mf = 0; mf < 2; mf++) {
                    uint32_t m = wm * 32 + mf * 16 + (lane & 15);
                    uint32_t u = (uint32_t)(kf * 2 + (lane >> 4));
                    uint32_t aoff = m * 64 + ((u ^ ((m >> 1) & 3)) << 4);
                    ldm_x4(a0[mf], smb + LSA(st, 0) + aoff);
                    ldm_x4(a1[mf], smb + LSA(st, 1) + aoff);
                }
#pragma unroll
                for (int nt = 0; nt < 2; nt++) {
                    uint32_t b0[4], b1[4];
                    int row = kf * 16 + (lane & 15);
                    int c   = wn * 4 + nt * 2 + (lane >> 4);
                    uint32_t boff = row * 256 + (uint32_t)(c ^ ((row & 7) << 1)) * 16;
                    ldm_x4t(b0, smb + LSB(st, 0) + boff);
                    ldm_x4t(b1, smb + LSB(st, 1) + boff);
#pragma unroll
                    for (int mf = 0; mf < 2; mf++) {
                        mma16816(acc[mf][nt * 2],     a0[mf], b0);
                        mma16816(acc[mf][nt * 2],     a1[mf], b0);
                        mma16816(acc[mf][nt * 2],     a0[mf], b1);
                        mma16816(acc[mf][nt * 2 + 1], a0[mf], b0 + 2);
                        mma16816(acc[mf][nt * 2 + 1], a1[mf], b0 + 2);
                        mma16816(acc[mf][nt * 2 + 1], a0[mf], b1 + 2);
                    }
                }
            }
        }
        __syncthreads();

        unsigned long long best[2][2] = {{0ull, 0ull}, {0ull, 0ull}};
#pragma unroll
        for (int mf = 0; mf < 2; mf++) {
#pragma unroll
            for (int nti = 0; nti < 4; nti++) {
                int r0 = wm * 32 + mf * 16 + (lane >> 2);
                int col = v0 + wn * 32 + nti * 8 + (lane & 3) * 2;
                float2 bb = *(const float2*)&bd[col];
                float2 o0 = make_float2(acc[mf][nti][0] + bb.x, acc[mf][nti][1] + bb.y);
                float2 o1 = make_float2(acc[mf][nti][2] + bb.x, acc[mf][nti][3] + bb.y);
                __stcs((float2*)&out[((size_t)r0 * TS + t) * VD + col], o0);
                __stcs((float2*)&out[((size_t)(r0 + 8) * TS + t) * VD + col], o1);
                unsigned long long e;
                e = enc_max(o0.x, col);     if (e > best[mf][0]) best[mf][0] = e;
                e = enc_max(o0.y, col + 1); if (e > best[mf][0]) best[mf][0] = e;
                e = enc_max(o1.x, col);     if (e > best[mf][1]) best[mf][1] = e;
                e = enc_max(o1.y, col + 1); if (e > best[mf][1]) best[mf][1] = e;
            }
        }
#pragma unroll
        for (int off = 1; off <= 2; off <<= 1) {
#pragma unroll
            for (int mf = 0; mf < 2; mf++)
#pragma unroll
                for (int h = 0; h < 2; h++) {
                    unsigned long long o = __shfl_xor_sync(0xFFFFFFFFu, best[mf][h], off);
                    if (o > best[mf][h]) best[mf][h] = o;
                }
        }
        if ((lane & 3) == 0) {
#pragma unroll
            for (int mf = 0; mf < 2; mf++)
#pragma unroll
                for (int h = 0; h < 2; h++) {
                    int row = wm * 32 + mf * 16 + h * 8 + (lane >> 2);
                    atomicMax(&samax[row], best[mf][h]);
                }
        }
        __syncthreads();
        if (tid < NB) atomicMax(&g_amax[tid], samax[tid]);
    }

    if (t == TS - 1) return;

    // ================= BARRIER 1: 314 arrivals =================
    __threadfence();
    __syncthreads();
    if (tid == 0) {
        unsigned int ticket = atomicAdd(&g_bar1, 1u);
        if (blockIdx.x < 64) {
            unsigned int target = (ticket / (unsigned)GRID_F + 1u) * (unsigned)GRID_F;
            while (*(volatile unsigned int*)&g_bar1 < target) __nanosleep(32);
            __threadfence();
        }
    }
    if (blockIdx.x >= 64) return;
    __syncthreads();

    // ================= PHASE 2: emb-half gate for t+1 (blocks 0-63) ==========
    {
        int bx = (int)blockIdx.x & 15, ks = (int)blockIdx.x >> 4;  // ks 0..3
        int row = tid >> 2;
        int idx = dec_idx(g_amax[row]);
        const float* a_src = emb + (size_t)idx * UD + ks * 128 + (tid & 3) * 32;
        gate_tile(smem, smb, tid, a_src, ks * 128, ks, bx * 128);
    }

    // ================= BARRIER 2: 64 arrivals =================
    __threadfence();
    __syncthreads();
    if (tid == 0) {
        unsigned int ticket = atomicAdd(&g_bar2, 1u);
        unsigned int target = (ticket / 64u + 1u) * 64u;
        while (*(volatile unsigned int*)&g_bar2 < target) __nanosleep(32);
        __threadfence();
    }
    __syncthreads();

    // ================= PHASE 3: LSTM update -> h_{t+1} (2 elem/thread) =======
    {
        int id = ((int)blockIdx.x * 256 + tid) * 2;
        int b = id >> 9, u = id & 511;
        size_t base = (size_t)b * ZN;
        float2 zi = {0.f, 0.f}, zf = {0.f, 0.f}, zg = {0.f, 0.f}, zo = {0.f, 0.f};
#pragma unroll
        for (int s = 0; s < GKS; s++) {
            float2 v;
            v = __ldcg((const float2*)&g_zpart[s][base + u]);        zi.x += v.x; zi.y += v.y;
            v = __ldcg((const float2*)&g_zpart[s][base + 512 + u]);  zf.x += v.x; zf.y += v.y;
            v = __ldcg((const float2*)&g_zpart[s][base + 1024 + u]); zg.x += v.x; zg.y += v.y;
            v = __ldcg((const float2*)&g_zpart[s][base + 1536 + u]); zo.x += v.x; zo.y += v.y;
        }
        float2 bi = *(const float2*)&b_lstm[u];
        float2 bf = *(const float2*)&b_lstm[512 + u];
        float2 bg = *(const float2*)&b_lstm[1024 + u];
        float2 bo = *(const float2*)&b_lstm[1536 + u];
        zi.x += bi.x; zi.y += bi.y; zf.x += bf.x; zf.y += bf.y;
        zg.x += bg.x; zg.y += bg.y; zo.x += bo.x; zo.y += bo.y;

        float2 cp = *(const float2*)&g_c[id];
        float2 hn, cn;
        {
            float si = 1.f / (1.f + expf(-zi.x));
            float sf = 1.f / (1.f + expf(-zf.x));
            float so = 1.f / (1.f + expf(-zo.x));
            cn.x = sf * cp.x + si * tanhf(zg.x);
            hn.x = so * tanhf(cn.x);
            si = 1.f / (1.f + expf(-zi.y));
            sf = 1.f / (1.f + expf(-zf.y));
            so = 1.f / (1.f + expf(-zo.y));
            cn.y = sf * cp.y + si * tanhf(zg.y);
            hn.y = so * tanhf(cn.y);
        }
        *(float2*)&g_c[id] = cn;
        *(float2*)&g_h[id] = hn;

        __nv_bfloat16 l0, h0b, l1, h1b;
        split2(hn.x, l0, h0b);
        split2(hn.y, l1, h1b);
        __nv_bfloat162 p0; p0.x = l0; p0.y = l1;
        __nv_bfloat162 p1; p1.x = h0b; p1.y = h1b;
        *(__nv_bfloat162*)&g_Al0[id] = p0;
        *(__nv_bfloat162*)&g_Al1[id] = p1;
        if (u == 0) g_amax[b] = 0ull;
    }
}

// ============================================================================
extern "C" void kernel_launch(void* const* d_in, const int* in_sizes, int n_in,
                              void* d_out, int out_size) {
    const float* h0  = (const float*)d_in[0];
    const float* c0  = (const float*)d_in[1];
    const float* emb = (const float*)d_in[2];
    const float* Wx  = (const float*)d_in[3];
    const float* Wh  = (const float*)d_in[4];
    const float* bl  = (const float*)d_in[5];
    const float* Wd  = (const float*)d_in[6];
    const float* bd  = (const float*)d_in[7];
    float* out = (float*)d_out;

    static bool attr_done = false;
    if (!attr_done) {
        cudaFuncSetAttribute(step_front_kernel,
                             cudaFuncAttributeMaxDynamicSharedMemorySize, FSMEM);
        cudaFuncSetAttribute(fused_step_kernel,
                             cudaFuncAttributeMaxDynamicSharedMemorySize, LSMEM);
        attr_done = true;
    }

    prep_WdT_kernel<<<(NTILES * NCHUNK * 32 * 16 + 255) / 256, 256>>>(Wd);
    prep_Wg_kernel<<<(GK * ZN + 255) / 256, 256>>>(Wx, Wh);
    step_front_kernel<<<dim3(16, GKS), 256, FSMEM>>>(h0, c0, emb, bl);

    for (int t = 0; t < TS; t++)
        fused_step_kernel<<<GRID_F, 256, LSMEM>>>(bd, out, emb, bl, t);
}

// round 17
// speedup vs baseline: 1.1291x; 1.1291x over previous
#include <cuda_runtime.h>
#include <cuda_bf16.h>
#include <cstdint>

#define NB 64
#define UD 512
#define VD 32000
#define TS 20
#define ZN 2048
#define GK 1024
#define GKS 8
#define NTILES 250
#define NCHUNK 16
#define PREP_WDT_BLOCKS 8000
#define PREP_WG_BLOCKS  8192

// ---------------- persistent device scratch ----------------
__device__ float g_h[NB * UD];
__device__ float g_c[NB * UD];
__device__ float g_zpart[GKS][NB * ZN];
__device__ unsigned long long g_amax[NB];
__device__ unsigned int g_barrier;   // step_front barrier (128 arrivals)
__device__ unsigned int g_bar1;      // fused barrier1 (250 arrivals/step)
__device__ unsigned int g_bar2;      // fused barrier2 (128 arrivals/step)
__device__ __align__(16) unsigned char g_WdT[(size_t)NTILES * NCHUNK * 2 * 8192];
__device__ __nv_bfloat16 g_Wg0[(size_t)GK * ZN];
__device__ __nv_bfloat16 g_Wg1[(size_t)GK * ZN];
__device__ __nv_bfloat16 g_Al0[NB * UD];
__device__ __nv_bfloat16 g_Al1[NB * UD];

// ---------------- helpers ----------------
__device__ __forceinline__ unsigned long long enc_max(float v, int col) {
    unsigned int u = __float_as_uint(v);
    unsigned int key = (u & 0x80000000u) ? ~u : (u | 0x80000000u);
    return ((unsigned long long)key << 32) |
           (unsigned long long)(0xFFFFFFFFu - (unsigned int)col);
}
__device__ __forceinline__ int dec_idx(unsigned long long e) {
    return (int)(0xFFFFFFFFu - (unsigned int)(e & 0xFFFFFFFFull));
}
__device__ __forceinline__ void split2(float v, __nv_bfloat16& b0, __nv_bfloat16& b1) {
    b0 = __float2bfloat16(v);
    b1 = __float2bfloat16(v - __bfloat162float(b0));
}
__device__ __forceinline__ uint32_t smem_u32(const void* p) {
    uint32_t a;
    asm("{ .reg .u64 t; cvta.to.shared.u64 t, %1; cvt.u32.u64 %0, t; }"
        : "=r"(a) : "l"(p));
    return a;
}
__device__ __forceinline__ void cp16(uint32_t dst, const void* src) {
    asm volatile("cp.async.cg.shared.global [%0], [%1], 16;" :: "r"(dst), "l"(src));
}
#define CP_COMMIT() asm volatile("cp.async.commit_group;" ::: "memory")
#define CP_WAIT(n)  asm volatile("cp.async.wait_group %0;" :: "n"(n) : "memory")

__device__ __forceinline__ void ldm_x4(uint32_t* r, uint32_t addr) {
    asm volatile("ldmatrix.sync.aligned.m8n8.x4.shared.b16 {%0,%1,%2,%3}, [%4];"
        : "=r"(r[0]), "=r"(r[1]), "=r"(r[2]), "=r"(r[3]) : "r"(addr));
}
__device__ __forceinline__ void ldm_x4t(uint32_t* r, uint32_t addr) {
    asm volatile("ldmatrix.sync.aligned.m8n8.x4.trans.shared.b16 {%0,%1,%2,%3}, [%4];"
        : "=r"(r[0]), "=r"(r[1]), "=r"(r[2]), "=r"(r[3]) : "r"(addr));
}
__device__ __forceinline__ void mma16816(float* c, const uint32_t* a, const uint32_t* b) {
    asm volatile(
        "mma.sync.aligned.m16n8k16.row.col.f32.bf16.bf16.f32 "
        "{%0,%1,%2,%3}, {%4,%5,%6,%7}, {%8,%9}, {%0,%1,%2,%3};"
        : "+f"(c[0]), "+f"(c[1]), "+f"(c[2]), "+f"(c[3])
        : "r"(a[0]), "r"(a[1]), "r"(a[2]), "r"(a[3]), "r"(b[0]), "r"(b[1]));
}

// ============================================================================
// one-time prep (merged): blocks [0, 8000) pack Wd; blocks [8000, 16192) split Wg
// ============================================================================
__global__ void __launch_bounds__(256) prep_all_kernel(
    const float* __restrict__ Wd,
    const float* __restrict__ Wx, const float* __restrict__ Wh)
{
    if (blockIdx.x < PREP_WDT_BLOCKS) {
        int id = blockIdx.x * blockDim.x + threadIdx.x;
        if (id >= NTILES * NCHUNK * 32 * 16) return;
        int c16 = id & 15;
        int r   = (id >> 4) & 31;
        int ch  = (id >> 9) & 15;
        int nt  = id >> 13;
        int k = ch * 32 + r;
        int n = nt * 128 + c16 * 8;
        const float* src = Wd + (size_t)k * VD + n;
        float4 v0 = *(const float4*)src;
        float4 v1 = *(const float4*)(src + 4);
        __nv_bfloat16 lo[8], hi[8];
        split2(v0.x, lo[0], hi[0]); split2(v0.y, lo[1], hi[1]);
        split2(v0.z, lo[2], hi[2]); split2(v0.w, lo[3], hi[3]);
        split2(v1.x, lo[4], hi[4]); split2(v1.y, lo[5], hi[5]);
        split2(v1.z, lo[6], hi[6]); split2(v1.w, lo[7], hi[7]);
        uint32_t off = (uint32_t)r * 256 + (uint32_t)(c16 ^ ((r & 7) << 1)) * 16;
        unsigned char* base = g_WdT + ((size_t)(nt * NCHUNK + ch) * 2) * 8192;
        *(uint4*)(base + off)        = *(uint4*)lo;
        *(uint4*)(base + 8192 + off) = *(uint4*)hi;
    } else {
        int id = (blockIdx.x - PREP_WDT_BLOCKS) * blockDim.x + threadIdx.x;
        if (id >= GK * ZN) return;
        int k = id >> 11, n = id & (ZN - 1);
        float v = (k < UD) ? Wx[(size_t)k * ZN + n] : Wh[(size_t)(k - UD) * ZN + n];
        __nv_bfloat16 b0, b1;
        split2(v, b0, b1);
        g_Wg0[id] = b0; g_Wg1[id] = b1;
    }
}

// ============================================================================
// STEP FRONT (t=0 only): proven 256-thread fused gate+barrier+update.
// ============================================================================
#define FA_ST 272
#define FB_ST 272
#define FSA(spl)      ((spl) * 17408u)
#define FSB(buf, spl) (34816u + ((buf) * 2 + (spl)) * 17408u)
#define FSMEM (34816 + 69632)

__global__ void __launch_bounds__(256, 1) step_front_kernel(
    const float* __restrict__ h0, const float* __restrict__ c0,
    const float* __restrict__ emb, const float* __restrict__ b_lstm)
{
    extern __shared__ unsigned char smem[];
    const uint32_t smb = smem_u32(smem);
    const int tid = threadIdx.x, wid = tid >> 5, lane = tid & 31;
    const int wm = wid & 1, wn = wid >> 1;
    const int n0 = blockIdx.x * 128;
    const int ks = blockIdx.y;
    const int kbase = ks * 128;

    const __nv_bfloat16* Bsrc[2] = { g_Wg0, g_Wg1 };

#pragma unroll
    for (int ch = 0; ch < 2; ch++) {
        int kc = kbase + ch * 64;
#pragma unroll
        for (int j = 0; j < 8; j++) {
            int i = tid + j * 256;
            int s = i >> 10, rem = i & 1023, r = rem >> 4, c16 = rem & 15;
            cp16(smb + FSB(ch, s) + r * FB_ST + c16 * 16,
                 Bsrc[s] + (size_t)(kc + r) * ZN + n0 + c16 * 8);
        }
        CP_COMMIT();
    }

    {
        const int row = tid >> 2;
        const int cbase = (tid & 3) * 32;
        const float* src = (ks < 4)
            ? emb + (size_t)1 * UD + kbase + cbase
            : h0 + row * UD + (ks - 4) * 128 + cbase;
        __nv_bfloat16* a0 = (__nv_bfloat16*)(smem + FSA(0) + row * FA_ST) + cbase;
        __nv_bfloat16* a1 = (__nv_bfloat16*)(smem + FSA(1) + row * FA_ST) + cbase;
#pragma unroll
        for (int q = 0; q < 8; q++) {
            float4 v = *(const float4*)(src + q * 4);
            __nv_bfloat16 lo, hi;
            split2(v.x, lo, hi); a0[q * 4 + 0] = lo; a1[q * 4 + 0] = hi;
            split2(v.y, lo, hi); a0[q * 4 + 1] = lo; a1[q * 4 + 1] = hi;
            split2(v.z, lo, hi); a0[q * 4 + 2] = lo; a1[q * 4 + 2] = hi;
            split2(v.w, lo, hi); a0[q * 4 + 3] = lo; a1[q * 4 + 3] = hi;
        }
    }

    float acc[2][4][4];
#pragma unroll
    for (int i = 0; i < 2; i++)
#pragma unroll
        for (int j = 0; j < 4; j++)
#pragma unroll
            for (int q = 0; q < 4; q++) acc[i][j][q] = 0.f;

#pragma unroll
    for (int ch = 0; ch < 2; ch++) {
        if (ch == 0) { CP_WAIT(1); } else { CP_WAIT(0); }
        __syncthreads();
#pragma unroll
        for (int kf = 0; kf < 4; kf++) {
            uint32_t a0[2][4], a1[2][4];
#pragma unroll
            for (int mf = 0; mf < 2; mf++) {
                uint32_t arow = (wm * 32 + mf * 16 + (lane & 15)) * FA_ST
                              + ch * 128 + kf * 32 + (lane >> 4) * 16;
                ldm_x4(a0[mf], smb + FSA(0) + arow);
                ldm_x4(a1[mf], smb + FSA(1) + arow);
            }
#pragma unroll
            for (int nt = 0; nt < 2; nt++) {
                uint32_t b0[4], b1[4];
                uint32_t boff = (kf * 16 + (lane & 15)) * FB_ST
                              + (wn * 32 + nt * 16) * 2 + (lane >> 4) * 16;
                ldm_x4t(b0, smb + FSB(ch, 0) + boff);
                ldm_x4t(b1, smb + FSB(ch, 1) + boff);
#pragma unroll
                for (int mf = 0; mf < 2; mf++) {
                    mma16816(acc[mf][nt * 2],     a0[mf], b0);
                    mma16816(acc[mf][nt * 2],     a1[mf], b0);
                    mma16816(acc[mf][nt * 2],     a0[mf], b1);
                    mma16816(acc[mf][nt * 2 + 1], a0[mf], b0 + 2);
                    mma16816(acc[mf][nt * 2 + 1], a1[mf], b0 + 2);
                    mma16816(acc[mf][nt * 2 + 1], a0[mf], b1 + 2);
                }
            }
        }
        if (ch == 0) __syncthreads();
    }

    float* zp = g_zpart[ks];
#pragma unroll
    for (int mf = 0; mf < 2; mf++) {
#pragma unroll
        for (int nti = 0; nti < 4; nti++) {
            int r0 = wm * 32 + mf * 16 + (lane >> 2);
            int col = n0 + wn * 32 + nti * 8 + (lane & 3) * 2;
            *(float2*)&zp[(size_t)r0 * ZN + col] =
                make_float2(acc[mf][nti][0], acc[mf][nti][1]);
            *(float2*)&zp[(size_t)(r0 + 8) * ZN + col] =
                make_float2(acc[mf][nti][2], acc[mf][nti][3]);
        }
    }

    __threadfence();
    __syncthreads();
    if (tid == 0) {
        unsigned int ticket = atomicAdd(&g_barrier, 1u);
        unsigned int target = (ticket / 128u + 1u) * 128u;
        while (*(volatile unsigned int*)&g_barrier < target) __nanosleep(32);
        __threadfence();
    }
    __syncthreads();

    {
        int blkLin = blockIdx.y * 16 + blockIdx.x;
        int id = blkLin * 256 + tid;
        int b = id >> 9, u = id & 511;
        size_t base = (size_t)b * ZN;
        float zi = 0.f, zf = 0.f, zg = 0.f, zo = 0.f;
#pragma unroll
        for (int s = 0; s < GKS; s++) {
            zi += __ldcg(&g_zpart[s][base + u]);
            zf += __ldcg(&g_zpart[s][base + 512 + u]);
            zg += __ldcg(&g_zpart[s][base + 1024 + u]);
            zo += __ldcg(&g_zpart[s][base + 1536 + u]);
        }
        zi += b_lstm[u];        zf += b_lstm[512 + u];
        zg += b_lstm[1024 + u]; zo += b_lstm[1536 + u];

        float cp = c0[id];
        float si = 1.f / (1.f + expf(-zi));
        float sf = 1.f / (1.f + expf(-zf));
        float so = 1.f / (1.f + expf(-zo));
        float tg = tanhf(zg);
        float cn = sf * cp + si * tg;
        float hn = so * tanhf(cn);
        g_c[id] = cn;
        g_h[id] = hn;

        __nv_bfloat16 lo, hi;
        split2(hn, lo, hi);
        g_Al0[id] = lo; g_Al1[id] = hi;
        if (u == 0) g_amax[b] = 0ull;
    }
}

// ============================================================================
// FUSED (3 blocks/SM, grid 250): logits(t) -> bar1(250) -> gate(t+1) [128 blk]
//   -> bar2(128) -> update. Identical to R15 (best: 639us).
// ============================================================================
#define LSA(st, spl) ((st) * 24576u + (spl) * 4096u)
#define LSB(st, spl) ((st) * 24576u + 8192u + (spl) * 8192u)
#define GA(spl)      ((spl) * 17408u)
#define GB(spl)      (34816u + (spl) * 17408u)
#define LSAMAX 73728
#define LSMEM  74240

__global__ void __launch_bounds__(256, 3) fused_step_kernel(
    const float* __restrict__ bd, float* __restrict__ out,
    const float* __restrict__ emb, const float* __restrict__ b_lstm, int t)
{
    extern __shared__ unsigned char smem[];
    const uint32_t smb = smem_u32(smem);
    unsigned long long* samax = (unsigned long long*)(smem + LSAMAX);
    const int tid = threadIdx.x, wid = tid >> 5, lane = tid & 31;
    const int wm = wid & 1, wn = wid >> 1;       // 2m x 4n
    const int nt_idx = (t & 1) ? (249 - (int)blockIdx.x) : (int)blockIdx.x;
    const int v0 = nt_idx * 128;

    if (tid < NB) samax[tid] = 0ull;

    {   // ================= PHASE 1: logits GEMM =================
        const __nv_bfloat16* Asrc[2] = { g_Al0, g_Al1 };
        const unsigned char* wt_base = g_WdT + ((size_t)nt_idx * NCHUNK * 2) * 8192;

        float acc[2][4][4];
#pragma unroll
        for (int i = 0; i < 2; i++)
#pragma unroll
            for (int j = 0; j < 4; j++)
#pragma unroll
                for (int q = 0; q < 4; q++) acc[i][j][q] = 0.f;

        auto load_chunk = [&](int ch, int st) {
            int kc = ch * 32;
#pragma unroll
            for (int j = 0; j < 2; j++) {
                int i = tid + j * 256;
                int s = i >> 8, rem = i & 255, r = rem >> 2, c4 = rem & 3;
                cp16(smb + LSA(st, s) + r * 64 + ((c4 ^ ((r >> 1) & 3)) << 4),
                     Asrc[s] + (size_t)r * UD + kc + c4 * 8);
            }
            const unsigned char* src = wt_base + ((size_t)ch * 2) * 8192;
#pragma unroll
            for (int j = 0; j < 4; j++) {
                int i = tid + j * 256;
                cp16(smb + LSB(st, 0) + (uint32_t)i * 16, src + (size_t)i * 16);
            }
            CP_COMMIT();
        };

        load_chunk(0, 0);
        load_chunk(1, 1);

#pragma unroll
        for (int ch = 0; ch < 16; ch++) {
            if (ch < 15) { CP_WAIT(1); } else { CP_WAIT(0); }
            __syncthreads();
            if (ch + 2 < 16) load_chunk(ch + 2, (ch + 2) % 3);
            const int st = ch % 3;
#pragma unroll
            for (int kf = 0; kf < 2; kf++) {
                uint32_t a0[2][4], a1[2][4];
#pragma unroll
                for (int mf = 0; mf < 2; mf++) {
                    uint32_t m = wm * 32 + mf * 16 + (lane & 15);
                    uint32_t u = (uint32_t)(kf * 2 + (lane >> 4));
                    uint32_t aoff = m * 64 + ((u ^ ((m >> 1) & 3)) << 4);
                    ldm_x4(a0[mf], smb + LSA(st, 0) + aoff);
                    ldm_x4(a1[mf], smb + LSA(st, 1) + aoff);
                }
#pragma unroll
                for (int nt = 0; nt < 2; nt++) {
                    uint32_t b0[4], b1[4];
                    int row = kf * 16 + (lane & 15);
                    int c   = wn * 4 + nt * 2 + (lane >> 4);
                    uint32_t boff = row * 256 + (uint32_t)(c ^ ((row & 7) << 1)) * 16;
                    ldm_x4t(b0, smb + LSB(st, 0) + boff);
                    ldm_x4t(b1, smb + LSB(st, 1) + boff);
#pragma unroll
                    for (int mf = 0; mf < 2; mf++) {
                        mma16816(acc[mf][nt * 2],     a0[mf], b0);
                        mma16816(acc[mf][nt * 2],     a1[mf], b0);
                        mma16816(acc[mf][nt * 2],     a0[mf], b1);
                        mma16816(acc[mf][nt * 2 + 1], a0[mf], b0 + 2);
                        mma16816(acc[mf][nt * 2 + 1], a1[mf], b0 + 2);
                        mma16816(acc[mf][nt * 2 + 1], a0[mf], b1 + 2);
                    }
                }
            }
        }
        __syncthreads();

        // epilogue: bias, streaming store, exact argmax
        unsigned long long best[2][2] = {{0ull, 0ull}, {0ull, 0ull}};
#pragma unroll
        for (int mf = 0; mf < 2; mf++) {
#pragma unroll
            for (int nti = 0; nti < 4; nti++) {
                int r0 = wm * 32 + mf * 16 + (lane >> 2);
                int col = v0 + wn * 32 + nti * 8 + (lane & 3) * 2;
                float2 bb = *(const float2*)&bd[col];
                float2 o0 = make_float2(acc[mf][nti][0] + bb.x, acc[mf][nti][1] + bb.y);
                float2 o1 = make_float2(acc[mf][nti][2] + bb.x, acc[mf][nti][3] + bb.y);
                __stcs((float2*)&out[((size_t)r0 * TS + t) * VD + col], o0);
                __stcs((float2*)&out[((size_t)(r0 + 8) * TS + t) * VD + col], o1);
                unsigned long long e;
                e = enc_max(o0.x, col);     if (e > best[mf][0]) best[mf][0] = e;
                e = enc_max(o0.y, col + 1); if (e > best[mf][0]) best[mf][0] = e;
                e = enc_max(o1.x, col);     if (e > best[mf][1]) best[mf][1] = e;
                e = enc_max(o1.y, col + 1); if (e > best[mf][1]) best[mf][1] = e;
            }
        }
#pragma unroll
        for (int off = 1; off <= 2; off <<= 1) {
#pragma unroll
            for (int mf = 0; mf < 2; mf++)
#pragma unroll
                for (int h = 0; h < 2; h++) {
                    unsigned long long o = __shfl_xor_sync(0xFFFFFFFFu, best[mf][h], off);
                    if (o > best[mf][h]) best[mf][h] = o;
                }
        }
        if ((lane & 3) == 0) {
#pragma unroll
            for (int mf = 0; mf < 2; mf++)
#pragma unroll
                for (int h = 0; h < 2; h++) {
                    int row = wm * 32 + mf * 16 + h * 8 + (lane >> 2);
                    atomicMax(&samax[row], best[mf][h]);
                }
        }
        __syncthreads();
        if (tid < NB) atomicMax(&g_amax[tid], samax[tid]);
    }

    if (t == TS - 1) return;

    // ================= BARRIER 1: all 250 blocks =================
    __threadfence();
    __syncthreads();
    if (tid == 0) {
        unsigned int ticket = atomicAdd(&g_bar1, 1u);
        if (blockIdx.x < 128) {
            unsigned int target = (ticket / 250u + 1u) * 250u;
            while (*(volatile unsigned int*)&g_bar1 < target) __nanosleep(32);
            __threadfence();
        }
    }
    if (blockIdx.x >= 128) return;
    __syncthreads();

    // ================= PHASE 2: gate GEMM for step t+1 =================
    {
        const int bx = (int)blockIdx.x & 15, ks = (int)blockIdx.x >> 4;
        const int n0g = bx * 128;
        const int kbase = ks * 128;
        const __nv_bfloat16* Bsrc[2] = { g_Wg0, g_Wg1 };

        auto load_gate_chunk = [&](int ch) {
            int kc = kbase + ch * 64;
#pragma unroll
            for (int j = 0; j < 8; j++) {
                int i = tid + j * 256;
                int s = i >> 10, rem = i & 1023, r = rem >> 4, c16 = rem & 15;
                cp16(smb + GB(s) + r * FB_ST + c16 * 16,
                     Bsrc[s] + (size_t)(kc + r) * ZN + n0g + c16 * 8);
            }
            CP_COMMIT();
        };
        load_gate_chunk(0);

        {
            const int row = tid >> 2;
            const int cbase = (tid & 3) * 32;
            const float* src;
            if (ks < 4) {
                int idx = dec_idx(g_amax[row]);
                src = emb + (size_t)idx * UD + kbase + cbase;
            } else {
                src = g_h + row * UD + (ks - 4) * 128 + cbase;
            }
            __nv_bfloat16* a0 = (__nv_bfloat16*)(smem + GA(0) + row * FA_ST) + cbase;
            __nv_bfloat16* a1 = (__nv_bfloat16*)(smem + GA(1) + row * FA_ST) + cbase;
#pragma unroll
            for (int q = 0; q < 8; q++) {
                float4 v = *(const float4*)(src + q * 4);
                __nv_bfloat16 lo, hi;
                split2(v.x, lo, hi); a0[q * 4 + 0] = lo; a1[q * 4 + 0] = hi;
                split2(v.y, lo, hi); a0[q * 4 + 1] = lo; a1[q * 4 + 1] = hi;
                split2(v.z, lo, hi); a0[q * 4 + 2] = lo; a1[q * 4 + 2] = hi;
                split2(v.w, lo, hi); a0[q * 4 + 3] = lo; a1[q * 4 + 3] = hi;
            }
        }

        float acc[2][4][4];
#pragma unroll
        for (int i = 0; i < 2; i++)
#pragma unroll
            for (int j = 0; j < 4; j++)
#pragma unroll
                for (int q = 0; q < 4; q++) acc[i][j][q] = 0.f;

#pragma unroll
        for (int ch = 0; ch < 2; ch++) {
            CP_WAIT(0);
            __syncthreads();
#pragma unroll
            for (int kf = 0; kf < 4; kf++) {
                uint32_t a0[2][4], a1[2][4];
#pragma unroll
                for (int mf = 0; mf < 2; mf++) {
                    uint32_t arow = (wm * 32 + mf * 16 + (lane & 15)) * FA_ST
                                  + ch * 128 + kf * 32 + (lane >> 4) * 16;
                    ldm_x4(a0[mf], smb + GA(0) + arow);
                    ldm_x4(a1[mf], smb + GA(1) + arow);
                }
#pragma unroll
                for (int nt = 0; nt < 2; nt++) {
                    uint32_t b0[4], b1[4];
                    uint32_t boff = (kf * 16 + (lane & 15)) * FB_ST
                                  + (wn * 32 + nt * 16) * 2 + (lane >> 4) * 16;
                    ldm_x4t(b0, smb + GB(0) + boff);
                    ldm_x4t(b1, smb + GB(1) + boff);
#pragma unroll
                    for (int mf = 0; mf < 2; mf++) {
                        mma16816(acc[mf][nt * 2],     a0[mf], b0);
                        mma16816(acc[mf][nt * 2],     a1[mf], b0);
                        mma16816(acc[mf][nt * 2],     a0[mf], b1);
                        mma16816(acc[mf][nt * 2 + 1], a0[mf], b0 + 2);
                        mma16816(acc[mf][nt * 2 + 1], a1[mf], b0 + 2);
                        mma16816(acc[mf][nt * 2 + 1], a0[mf], b1 + 2);
                    }
                }
            }
            if (ch == 0) {
                __syncthreads();           // all reads of chunk 0 done
                load_gate_chunk(1);        // overwrite GB with chunk 1
            }
        }

        float* zp = g_zpart[(int)blockIdx.x >> 4];
#pragma unroll
        for (int mf = 0; mf < 2; mf++) {
#pragma unroll
            for (int nti = 0; nti < 4; nti++) {
                int r0 = wm * 32 + mf * 16 + (lane >> 2);
                int col = n0g + wn * 32 + nti * 8 + (lane & 3) * 2;
                *(float2*)&zp[(size_t)r0 * ZN + col] =
                    make_float2(acc[mf][nti][0], acc[mf][nti][1]);
                *(float2*)&zp[(size_t)(r0 + 8) * ZN + col] =
                    make_float2(acc[mf][nti][2], acc[mf][nti][3]);
            }
        }
    }

    // ================= BARRIER 2: the 128 gate blocks =================
    __threadfence();
    __syncthreads();
    if (tid == 0) {
        unsigned int ticket = atomicAdd(&g_bar2, 1u);
        unsigned int target = (ticket / 128u + 1u) * 128u;
        while (*(volatile unsigned int*)&g_bar2 < target) __nanosleep(32);
        __threadfence();
    }
    __syncthreads();

    // ================= PHASE 3: LSTM update -> h_{t+1} =================
    {
        int id = (int)blockIdx.x * 256 + tid;
        int b = id >> 9, u = id & 511;
        size_t base = (size_t)b * ZN;
        float zi = 0.f, zf = 0.f, zg = 0.f, zo = 0.f;
#pragma unroll
        for (int s = 0; s < GKS; s++) {
            zi += __ldcg(&g_zpart[s][base + u]);
            zf += __ldcg(&g_zpart[s][base + 512 + u]);
            zg += __ldcg(&g_zpart[s][base + 1024 + u]);
            zo += __ldcg(&g_zpart[s][base + 1536 + u]);
        }
        zi += b_lstm[u];        zf += b_lstm[512 + u];
        zg += b_lstm[1024 + u]; zo += b_lstm[1536 + u];

        float cp = g_c[id];
        float si = 1.f / (1.f + expf(-zi));
        float sf = 1.f / (1.f + expf(-zf));
        float so = 1.f / (1.f + expf(-zo));
        float tg = tanhf(zg);
        float cn = sf * cp + si * tg;
        float hn = so * tanhf(cn);
        g_c[id] = cn;
        g_h[id] = hn;

        __nv_bfloat16 lo, hi;
        split2(hn, lo, hi);
        g_Al0[id] = lo; g_Al1[id] = hi;
        if (u == 0) g_amax[b] = 0ull;
    }
}

// ============================================================================
extern "C" void kernel_launch(void* const* d_in, const int* in_sizes, int n_in,
                              void* d_out, int out_size) {
    const float* h0  = (const float*)d_in[0];
    const float* c0  = (const float*)d_in[1];
    const float* emb = (const float*)d_in[2];
    const float* Wx  = (const float*)d_in[3];
    const float* Wh  = (const float*)d_in[4];
    const float* bl  = (const float*)d_in[5];
    const float* Wd  = (const float*)d_in[6];
    const float* bd  = (const float*)d_in[7];
    float* out = (float*)d_out;

    static bool attr_done = false;
    if (!attr_done) {
        cudaFuncSetAttribute(step_front_kernel,
                             cudaFuncAttributeMaxDynamicSharedMemorySize, FSMEM);
        cudaFuncSetAttribute(fused_step_kernel,
                             cudaFuncAttributeMaxDynamicSharedMemorySize, LSMEM);
        attr_done = true;
    }

    prep_all_kernel<<<PREP_WDT_BLOCKS + PREP_WG_BLOCKS, 256>>>(Wd, Wx, Wh);
    step_front_kernel<<<dim3(16, GKS), 256, FSMEM>>>(h0, c0, emb, bl);

    for (int t = 0; t < TS; t++)
        fused_step_kernel<<<NTILES, 256, LSMEM>>>(bd, out, emb, bl, t);
}